// round 5
// baseline (speedup 1.0000x reference)
#include <cuda_runtime.h>

#define T_STEPS 8192
#define IN_DIM  128
#define H_DIM   1024
#define NLAYERS 3
#define NCTA    128
#define TPB     256
#define NWARP   8

// Static device scratch (allocation-free rule).
__device__ float g_bufA[(size_t)T_STEPS * H_DIM];      // layer 0 output
__device__ float g_bufB[(size_t)T_STEPS * H_DIM];      // layer 1 output
__device__ float g_bufC[(size_t)T_STEPS * H_DIM];      // layer 2 output
__device__ float g_gi[(size_t)T_STEPS * 2 * H_DIM];    // per-layer input projection (reused)
__device__ unsigned g_flag[8 * 32];                    // chunk flags, 128B apart
__device__ unsigned g_bar_cnt;
__device__ unsigned g_bar_gen;

__device__ __forceinline__ float dot4(float4 a, float4 b) {
    return a.x * b.x + a.y * b.y + a.z * b.z + a.w * b.w;
}

__device__ __forceinline__ float fast_sigmoid(float x) {
    // limits safe: __expf(+big)=inf -> 0 ; __expf(-big)=0 -> 1
    return __fdividef(1.f, 1.f + __expf(-x));
}
__device__ __forceinline__ float fast_tanh(float x) {
    x = fminf(fmaxf(x, -15.f), 15.f);          // avoid inf/inf
    float e2 = __expf(2.f * x);
    return __fdividef(e2 - 1.f, e2 + 1.f);
}

// Full grid barrier (layer boundaries only). All NCTA=128 blocks are co-resident:
// grid size < SM count, so every CTA is scheduled in wave 1.
__device__ __forceinline__ void grid_barrier(unsigned target) {
    __syncthreads();
    if (threadIdx.x == 0) {
        __threadfence();
        unsigned prev = atomicAdd(&g_bar_cnt, 1u);
        if (prev == NCTA - 1) {
            g_bar_cnt = 0;
            __threadfence();
            *(volatile unsigned*)&g_bar_gen = target;
        } else {
            while (*(volatile unsigned*)&g_bar_gen < target) { }
        }
        __threadfence();
    }
    __syncthreads();
}

__global__ void __launch_bounds__(TPB, 1)
mgu_persistent_kernel(const float* __restrict__ S,
                      const float* __restrict__ h0,
                      const float* __restrict__ w_ih0,
                      const float* __restrict__ w_hh0,
                      const float* __restrict__ b_ih0,
                      const float* __restrict__ b_hh0,
                      const float* __restrict__ w_ih_r,
                      const float* __restrict__ w_hh_r,
                      const float* __restrict__ b_ih_r,
                      const float* __restrict__ b_hh_r,
                      const float* __restrict__ w_out,
                      const float* __restrict__ b_out,
                      float* __restrict__ out)
{
    __shared__ float s_part[2][16][9];   // scan cross-warp partials, padded stride 9
    __shared__ float s_gi[8][16][9];     // gi batch partials (8 timesteps/epoch)
    __shared__ float s_bgi[16];          // gi bias per local row

    const int tid  = threadIdx.x;
    const int wid  = tid >> 5;
    const int lane = tid & 31;
    const int h    = lane >> 4;          // column half within warp chunk
    const int r    = lane & 15;          // row index (0-7: f rows, 8-15: n rows)
    const int c0   = blockIdx.x * 8;     // first h-index owned by this CTA
    const int grow = (r < 8) ? (c0 + r) : (H_DIM + c0 + (r - 8));

    unsigned bgen = 0;

    for (int l = 0; l < NLAYERS; l++) {
        const float *wih, *whh, *bih, *bhh, *xbuf;
        float* obuf;
        if (l == 0) {
            wih = w_ih0; whh = w_hh0; bih = b_ih0; bhh = b_hh0;
            xbuf = S; obuf = g_bufA;
        } else if (l == 1) {
            wih = w_ih_r; whh = w_hh_r; bih = b_ih_r; bhh = b_hh_r;
            xbuf = g_bufA; obuf = g_bufB;
        } else {
            wih = w_ih_r + (size_t)2048 * 1024; whh = w_hh_r + (size_t)2048 * 1024;
            bih = b_ih_r + 2048;                bhh = b_hh_r + 2048;
            xbuf = g_bufB; obuf = g_bufC;
        }

        const float bgi = bih[grow];     // gi bias for this lane's row
        float bhf = 0.f, bhn = 0.f, hreg = 0.f;
        if (tid < 8) {                   // combine-thread constants
            bhf  = bhh[c0 + tid];
            bhn  = bhh[H_DIM + c0 + tid];
            hreg = h0[l * H_DIM + c0 + tid];
        }
        if (tid < 16) s_bgi[tid] = bgi;  // for tid<16, grow == growOf(tid)
        __syncthreads();

        float4 wv[16];                   // lane's weight slice (registers)

        // ================= gi phase: g_gi[t][.] = x[t] @ wih.T + b_ih =================
        if (l == 0) {
            // KIN=128: one warp covers a full row dot -> warps split over t, no sync.
            #pragma unroll
            for (int j = 0; j < 16; j++)
                wv[j] = reinterpret_cast<const float4*>(wih)[grow * (IN_DIM / 4) + 16 * h + j];
            for (int t = wid; t < T_STEPS; t += NWARP) {
                const float4* vp = reinterpret_cast<const float4*>(xbuf)
                                 + (size_t)t * (IN_DIM / 4) + 16 * h;
                float a0 = 0.f, a1 = 0.f, a2 = 0.f, a3 = 0.f;
                #pragma unroll
                for (int j = 0; j < 16; j += 4) {
                    a0 += dot4(wv[j],     vp[j]);
                    a1 += dot4(wv[j + 1], vp[j + 1]);
                    a2 += dot4(wv[j + 2], vp[j + 2]);
                    a3 += dot4(wv[j + 3], vp[j + 3]);
                }
                float acc = (a0 + a1) + (a2 + a3);
                acc += __shfl_xor_sync(0xffffffffu, acc, 16);
                if (lane < 16)
                    g_gi[(size_t)t * (2 * H_DIM) + grow] = acc + bgi;
            }
        } else {
            // KIN=1024: warps split columns; batch 8 timesteps per sync epoch.
            #pragma unroll
            for (int j = 0; j < 16; j++)
                wv[j] = reinterpret_cast<const float4*>(wih)[grow * (H_DIM / 4) + 32 * wid + 16 * h + j];
            for (int t0 = 0; t0 < T_STEPS; t0 += 8) {
                #pragma unroll
                for (int dt = 0; dt < 8; dt++) {
                    const float4* vp = reinterpret_cast<const float4*>(xbuf)
                                     + (size_t)(t0 + dt) * (H_DIM / 4) + 32 * wid + 16 * h;
                    float a0 = 0.f, a1 = 0.f, a2 = 0.f, a3 = 0.f;
                    #pragma unroll
                    for (int j = 0; j < 16; j += 4) {
                        a0 += dot4(wv[j],     vp[j]);
                        a1 += dot4(wv[j + 1], vp[j + 1]);
                        a2 += dot4(wv[j + 2], vp[j + 2]);
                        a3 += dot4(wv[j + 3], vp[j + 3]);
                    }
                    float acc = (a0 + a1) + (a2 + a3);
                    acc += __shfl_xor_sync(0xffffffffu, acc, 16);
                    if (lane < 16) s_gi[dt][lane][wid] = acc;
                }
                __syncthreads();
                if (tid < 128) {
                    const int dt  = tid >> 4;
                    const int row = tid & 15;
                    const int gw  = (row < 8) ? (c0 + row) : (H_DIM + c0 + (row - 8));
                    float s = 0.f;
                    #pragma unroll
                    for (int w2 = 0; w2 < 8; w2++) s += s_gi[dt][row][w2];
                    g_gi[(size_t)(t0 + dt) * (2 * H_DIM) + gw] = s + s_bgi[row];
                }
                __syncthreads();
            }
        }
        // Seal gi writes before the scan reads them.
        __syncthreads();

        // ================= scan =================
        #pragma unroll
        for (int j = 0; j < 16; j++)
            wv[j] = reinterpret_cast<const float4*>(whh)[grow * (H_DIM / 4) + 32 * wid + 16 * h + j];

        const unsigned fbase = (unsigned)l * 16u * (unsigned)T_STEPS;
        for (int t = 0; t < T_STEPS; t++) {
            // prefetch gi (no dependency on flags; same-CTA data)
            float gif = 0.f, gin = 0.f;
            if (tid < 8) {
                gif = g_gi[(size_t)t * (2 * H_DIM) + c0 + tid];
                gin = g_gi[(size_t)t * (2 * H_DIM) + H_DIM + c0 + tid];
            }
            // wait until the 16 producer CTAs of chunk `wid` published h_{t-1}
            const unsigned target = fbase + 16u * (unsigned)t;
            if (lane == 0) {
                while (*(volatile unsigned*)&g_flag[wid * 32] < target) { }
                __threadfence();   // acquire; also invalidates L1D (CCTL.IVALL)
            }
            __syncwarp();

            const float* hsrc = (t == 0) ? (h0 + l * H_DIM)
                                         : (obuf + (size_t)(t - 1) * H_DIM);
            const float4* vp = reinterpret_cast<const float4*>(hsrc) + 32 * wid + 16 * h;
            float a0 = 0.f, a1 = 0.f, a2 = 0.f, a3 = 0.f;
            #pragma unroll
            for (int j = 0; j < 16; j += 4) {
                a0 += dot4(wv[j],     vp[j]);
                a1 += dot4(wv[j + 1], vp[j + 1]);
                a2 += dot4(wv[j + 2], vp[j + 2]);
                a3 += dot4(wv[j + 3], vp[j + 3]);
            }
            float acc = (a0 + a1) + (a2 + a3);
            acc += __shfl_xor_sync(0xffffffffu, acc, 16);
            if (lane < 16) s_part[t & 1][lane][wid] = acc;
            __syncthreads();

            if (tid < 8) {
                float ghf = bhf, ghn = bhn;
                #pragma unroll
                for (int w2 = 0; w2 < 8; w2++) {
                    ghf += s_part[t & 1][tid][w2];
                    ghn += s_part[t & 1][tid + 8][w2];
                }
                float f  = fast_sigmoid(gif + ghf);
                float n  = fast_tanh(gin + f * ghn);
                float hy = n + (1.f - f) * (hreg - n);
                hreg = hy;
                obuf[(size_t)t * H_DIM + c0 + tid] = hy;
            }
            if (wid == 0) __syncwarp();   // order combine stores before the release
            if (tid == 0) {
                __threadfence();
                atomicAdd(&g_flag[(blockIdx.x >> 4) * 32], 1u);
            }
        }
        grid_barrier(++bgen);   // obuf(l) complete device-wide
    }

    // ================= epilogue: out[t] = bufC[t] . w_out + b_out =================
    float4 wo[8];
    #pragma unroll
    for (int k = 0; k < 8; k++)
        wo[k] = reinterpret_cast<const float4*>(w_out)[lane + 32 * k];
    const float bo = b_out[0];
    for (int tt = wid; tt < 64; tt += NWARP) {
        const int t = blockIdx.x * 64 + tt;
        const float4* xr = reinterpret_cast<const float4*>(g_bufC) + (size_t)t * (H_DIM / 4);
        float a0 = 0.f, a1 = 0.f, a2 = 0.f, a3 = 0.f;
        #pragma unroll
        for (int k = 0; k < 8; k += 4) {
            a0 += dot4(wo[k],     xr[lane + 32 * k]);
            a1 += dot4(wo[k + 1], xr[lane + 32 * (k + 1)]);
            a2 += dot4(wo[k + 2], xr[lane + 32 * (k + 2)]);
            a3 += dot4(wo[k + 3], xr[lane + 32 * (k + 3)]);
        }
        float acc = (a0 + a1) + (a2 + a3);
        #pragma unroll
        for (int off = 16; off > 0; off >>= 1)
            acc += __shfl_xor_sync(0xffffffffu, acc, off);
        if (lane == 0) out[t] = acc + bo;
    }
}

// Zero barrier/flag state every launch (graph replays).
__global__ void mgu_reset_kernel() {
    for (int i = 0; i < 8 * 32; i++) g_flag[i] = 0u;
    g_bar_cnt = 0u;
    g_bar_gen = 0u;
}

extern "C" void kernel_launch(void* const* d_in, const int* in_sizes, int n_in,
                              void* d_out, int out_size) {
    const float* S      = (const float*)d_in[0];
    const float* h0     = (const float*)d_in[1];
    const float* w_ih0  = (const float*)d_in[2];
    const float* w_hh0  = (const float*)d_in[3];
    const float* b_ih0  = (const float*)d_in[4];
    const float* b_hh0  = (const float*)d_in[5];
    const float* w_ih_r = (const float*)d_in[6];
    const float* w_hh_r = (const float*)d_in[7];
    const float* b_ih_r = (const float*)d_in[8];
    const float* b_hh_r = (const float*)d_in[9];
    const float* w_out  = (const float*)d_in[10];
    const float* b_out  = (const float*)d_in[11];
    float* out = (float*)d_out;

    mgu_reset_kernel<<<1, 1>>>();
    mgu_persistent_kernel<<<NCTA, TPB>>>(
        S, h0, w_ih0, w_hh0, b_ih0, b_hh0,
        w_ih_r, w_hh_r, b_ih_r, b_hh_r, w_out, b_out, out);
}

// round 6
// speedup vs baseline: 1.1380x; 1.1380x over previous
#include <cuda_runtime.h>

#define T_STEPS 8192
#define IN_DIM  128
#define H_DIM   1024
#define NLAYERS 3
#define NCTA    128
#define TPB     256
#define NWARP   8

// Static device scratch (allocation-free rule).
__device__ float g_bufA[(size_t)T_STEPS * H_DIM];      // layer 0 output
__device__ float g_bufB[(size_t)T_STEPS * H_DIM];      // layer 1 output
__device__ float g_bufC[(size_t)T_STEPS * H_DIM];      // layer 2 output
__device__ float g_gi[(size_t)T_STEPS * 2 * H_DIM];    // per-layer input projection (reused)
__device__ unsigned g_step[32];                        // single step counter (padded line)
__device__ unsigned g_bar_cnt;
__device__ unsigned g_bar_gen;

__device__ __forceinline__ float dot4(float4 a, float4 b) {
    return a.x * b.x + a.y * b.y + a.z * b.z + a.w * b.w;
}

__device__ __forceinline__ float fast_sigmoid(float x) {
    return __fdividef(1.f, 1.f + __expf(-x));
}
__device__ __forceinline__ float fast_tanh(float x) {
    x = fminf(fmaxf(x, -15.f), 15.f);
    float e2 = __expf(2.f * x);
    return __fdividef(e2 - 1.f, e2 + 1.f);
}

// Scoped sync primitives: no MEMBAR.GPU / CCTL.IVALL on the hot path.
__device__ __forceinline__ unsigned ld_acquire_gpu(const unsigned* p) {
    unsigned v;
    asm volatile("ld.acquire.gpu.global.u32 %0, [%1];" : "=r"(v) : "l"(p) : "memory");
    return v;
}
__device__ __forceinline__ void red_release_gpu_add(unsigned* p, unsigned v) {
    asm volatile("red.release.gpu.global.add.u32 [%0], %1;" :: "l"(p), "r"(v) : "memory");
}

// Full grid barrier (layer boundaries only; 3 uses). All 128 CTAs co-resident
// (grid < SM count -> wave 1).
__device__ __forceinline__ void grid_barrier(unsigned target) {
    __syncthreads();
    if (threadIdx.x == 0) {
        __threadfence();
        unsigned prev = atomicAdd(&g_bar_cnt, 1u);
        if (prev == NCTA - 1) {
            g_bar_cnt = 0;
            __threadfence();
            *(volatile unsigned*)&g_bar_gen = target;
        } else {
            while (*(volatile unsigned*)&g_bar_gen < target) { }
        }
        __threadfence();
    }
    __syncthreads();
}

__global__ void __launch_bounds__(TPB, 1)
mgu_persistent_kernel(const float* __restrict__ S,
                      const float* __restrict__ h0,
                      const float* __restrict__ w_ih0,
                      const float* __restrict__ w_hh0,
                      const float* __restrict__ b_ih0,
                      const float* __restrict__ b_hh0,
                      const float* __restrict__ w_ih_r,
                      const float* __restrict__ w_hh_r,
                      const float* __restrict__ b_ih_r,
                      const float* __restrict__ b_hh_r,
                      const float* __restrict__ w_out,
                      const float* __restrict__ b_out,
                      float* __restrict__ out)
{
    __shared__ float s_part[2][16][9];   // scan cross-warp partials, padded stride 9
    __shared__ float s_gi[8][16][9];     // gi batch partials (8 timesteps/epoch)
    __shared__ float s_bgi[16];          // gi bias per local row

    const int tid  = threadIdx.x;
    const int wid  = tid >> 5;
    const int lane = tid & 31;
    const int h    = lane >> 4;          // column half within warp chunk
    const int r    = lane & 15;          // row index (0-7: f rows, 8-15: n rows)
    const int c0   = blockIdx.x * 8;     // first h-index owned by this CTA
    const int grow = (r < 8) ? (c0 + r) : (H_DIM + c0 + (r - 8));

    unsigned bgen = 0;

    for (int l = 0; l < NLAYERS; l++) {
        const float *wih, *whh, *bih, *bhh, *xbuf;
        float* obuf;
        if (l == 0) {
            wih = w_ih0; whh = w_hh0; bih = b_ih0; bhh = b_hh0;
            xbuf = S; obuf = g_bufA;
        } else if (l == 1) {
            wih = w_ih_r; whh = w_hh_r; bih = b_ih_r; bhh = b_hh_r;
            xbuf = g_bufA; obuf = g_bufB;
        } else {
            wih = w_ih_r + (size_t)2048 * 1024; whh = w_hh_r + (size_t)2048 * 1024;
            bih = b_ih_r + 2048;                bhh = b_hh_r + 2048;
            xbuf = g_bufB; obuf = g_bufC;
        }

        const float bgi = bih[grow];
        float bhf = 0.f, bhn = 0.f, hreg = 0.f;
        if (tid < 8) {
            bhf  = bhh[c0 + tid];
            bhn  = bhh[H_DIM + c0 + tid];
            hreg = h0[l * H_DIM + c0 + tid];
        }
        if (tid < 16) s_bgi[tid] = bgi;
        __syncthreads();

        float4 wv[16];                   // lane's weight slice (registers)

        // ================= gi phase: g_gi[t][.] = x[t] @ wih.T + b_ih =================
        if (l == 0) {
            #pragma unroll
            for (int j = 0; j < 16; j++)
                wv[j] = reinterpret_cast<const float4*>(wih)[grow * (IN_DIM / 4) + 16 * h + j];
            for (int t = wid; t < T_STEPS; t += NWARP) {
                const float4* vp = reinterpret_cast<const float4*>(xbuf)
                                 + (size_t)t * (IN_DIM / 4) + 16 * h;
                float a0 = 0.f, a1 = 0.f, a2 = 0.f, a3 = 0.f;
                #pragma unroll
                for (int j = 0; j < 16; j += 4) {
                    a0 += dot4(wv[j],     vp[j]);
                    a1 += dot4(wv[j + 1], vp[j + 1]);
                    a2 += dot4(wv[j + 2], vp[j + 2]);
                    a3 += dot4(wv[j + 3], vp[j + 3]);
                }
                float acc = (a0 + a1) + (a2 + a3);
                acc += __shfl_xor_sync(0xffffffffu, acc, 16);
                if (lane < 16)
                    g_gi[(size_t)t * (2 * H_DIM) + grow] = acc + bgi;
            }
        } else {
            #pragma unroll
            for (int j = 0; j < 16; j++)
                wv[j] = reinterpret_cast<const float4*>(wih)[grow * (H_DIM / 4) + 32 * wid + 16 * h + j];
            for (int t0 = 0; t0 < T_STEPS; t0 += 8) {
                #pragma unroll
                for (int dt = 0; dt < 8; dt++) {
                    const float4* vp = reinterpret_cast<const float4*>(xbuf)
                                     + (size_t)(t0 + dt) * (H_DIM / 4) + 32 * wid + 16 * h;
                    float a0 = 0.f, a1 = 0.f, a2 = 0.f, a3 = 0.f;
                    #pragma unroll
                    for (int j = 0; j < 16; j += 4) {
                        a0 += dot4(wv[j],     vp[j]);
                        a1 += dot4(wv[j + 1], vp[j + 1]);
                        a2 += dot4(wv[j + 2], vp[j + 2]);
                        a3 += dot4(wv[j + 3], vp[j + 3]);
                    }
                    float acc = (a0 + a1) + (a2 + a3);
                    acc += __shfl_xor_sync(0xffffffffu, acc, 16);
                    if (lane < 16) s_gi[dt][lane][wid] = acc;
                }
                __syncthreads();
                if (tid < 128) {
                    const int dt  = tid >> 4;
                    const int row = tid & 15;
                    const int gw  = (row < 8) ? (c0 + row) : (H_DIM + c0 + (row - 8));
                    float s = 0.f;
                    #pragma unroll
                    for (int w2 = 0; w2 < 8; w2++) s += s_gi[dt][row][w2];
                    g_gi[(size_t)(t0 + dt) * (2 * H_DIM) + gw] = s + s_bgi[row];
                }
                __syncthreads();
            }
        }
        __syncthreads();   // seal gi before scan reads

        // ================= scan =================
        #pragma unroll
        for (int j = 0; j < 16; j++)
            wv[j] = reinterpret_cast<const float4*>(whh)[grow * (H_DIM / 4) + 32 * wid + 16 * h + j];

        const unsigned fbase = (unsigned)l * (unsigned)NCTA * (unsigned)T_STEPS;
        for (int t = 0; t < T_STEPS; t++) {
            // prefetch gi (same-CTA data, no flag dependency)
            float gif = 0.f, gin = 0.f;
            if (tid < 8) {
                gif = g_gi[(size_t)t * (2 * H_DIM) + c0 + tid];
                gin = g_gi[(size_t)t * (2 * H_DIM) + H_DIM + c0 + tid];
            }
            // single poller: wait until all 128 CTAs published h_{t-1}
            if (t > 0) {
                const unsigned target = fbase + (unsigned)NCTA * (unsigned)t;
                if (tid == 0) {
                    while (ld_acquire_gpu(&g_step[0]) < target) { }
                }
                __syncthreads();   // release CTA; orders loads after acquire
            }

            const float* hsrc = (t == 0) ? (h0 + l * H_DIM)
                                         : (obuf + (size_t)(t - 1) * H_DIM);
            const float4* vp = reinterpret_cast<const float4*>(hsrc) + 32 * wid + 16 * h;
            float a0 = 0.f, a1 = 0.f, a2 = 0.f, a3 = 0.f;
            #pragma unroll
            for (int j = 0; j < 16; j += 4) {
                a0 += dot4(__ldcg(vp + j),     wv[j]);
                a1 += dot4(__ldcg(vp + j + 1), wv[j + 1]);
                a2 += dot4(__ldcg(vp + j + 2), wv[j + 2]);
                a3 += dot4(__ldcg(vp + j + 3), wv[j + 3]);
            }
            float acc = (a0 + a1) + (a2 + a3);
            acc += __shfl_xor_sync(0xffffffffu, acc, 16);
            if (lane < 16) s_part[t & 1][lane][wid] = acc;
            __syncthreads();

            if (tid < 8) {
                float ghf = bhf, ghn = bhn;
                #pragma unroll
                for (int w2 = 0; w2 < 8; w2++) {
                    ghf += s_part[t & 1][tid][w2];
                    ghn += s_part[t & 1][tid + 8][w2];
                }
                float f  = fast_sigmoid(gif + ghf);
                float n  = fast_tanh(gin + f * ghn);
                float hy = n + (1.f - f) * (hreg - n);
                hreg = hy;
                obuf[(size_t)t * H_DIM + c0 + tid] = hy;
            }
            if (wid == 0) __syncwarp();   // teammate stores happen-before the release
            if (tid == 0)
                red_release_gpu_add(&g_step[0], 1u);
        }
        grid_barrier(++bgen);   // obuf(l) complete device-wide
    }

    // ================= epilogue: out[t] = bufC[t] . w_out + b_out =================
    float4 wo[8];
    #pragma unroll
    for (int k = 0; k < 8; k++)
        wo[k] = reinterpret_cast<const float4*>(w_out)[lane + 32 * k];
    const float bo = b_out[0];
    for (int tt = wid; tt < 64; tt += NWARP) {
        const int t = blockIdx.x * 64 + tt;
        const float4* xr = reinterpret_cast<const float4*>(g_bufC) + (size_t)t * (H_DIM / 4);
        float a0 = 0.f, a1 = 0.f, a2 = 0.f, a3 = 0.f;
        #pragma unroll
        for (int k = 0; k < 8; k += 4) {
            a0 += dot4(wo[k],     __ldcg(xr + lane + 32 * k));
            a1 += dot4(wo[k + 1], __ldcg(xr + lane + 32 * (k + 1)));
            a2 += dot4(wo[k + 2], __ldcg(xr + lane + 32 * (k + 2)));
            a3 += dot4(wo[k + 3], __ldcg(xr + lane + 32 * (k + 3)));
        }
        float acc = (a0 + a1) + (a2 + a3);
        #pragma unroll
        for (int off = 16; off > 0; off >>= 1)
            acc += __shfl_xor_sync(0xffffffffu, acc, off);
        if (lane == 0) out[t] = acc + bo;
    }
}

// Zero barrier/flag state every launch (graph replays).
__global__ void mgu_reset_kernel() {
    for (int i = 0; i < 32; i++) g_step[i] = 0u;
    g_bar_cnt = 0u;
    g_bar_gen = 0u;
}

extern "C" void kernel_launch(void* const* d_in, const int* in_sizes, int n_in,
                              void* d_out, int out_size) {
    const float* S      = (const float*)d_in[0];
    const float* h0     = (const float*)d_in[1];
    const float* w_ih0  = (const float*)d_in[2];
    const float* w_hh0  = (const float*)d_in[3];
    const float* b_ih0  = (const float*)d_in[4];
    const float* b_hh0  = (const float*)d_in[5];
    const float* w_ih_r = (const float*)d_in[6];
    const float* w_hh_r = (const float*)d_in[7];
    const float* b_ih_r = (const float*)d_in[8];
    const float* b_hh_r = (const float*)d_in[9];
    const float* w_out  = (const float*)d_in[10];
    const float* b_out  = (const float*)d_in[11];
    float* out = (float*)d_out;

    mgu_reset_kernel<<<1, 1>>>();
    mgu_persistent_kernel<<<NCTA, TPB>>>(
        S, h0, w_ih0, w_hh0, b_ih0, b_hh0,
        w_ih_r, w_hh_r, b_ih_r, b_hh_r, w_out, b_out, out);
}